// round 10
// baseline (speedup 1.0000x reference)
#include <cuda_runtime.h>
#include <cuda_bf16.h>
#include <math.h>
#include <stdint.h>

// Problem constants
#define BB 16
#define CC 512
#define HW 1024
#define P  16384            // positions
#define NN 16384            // codebook size
#define DD 32               // embedding dim
#define OUT_ELEMS (BB*CC*HW)

#define MTILE 128           // positions per CTA
#define CHUNK 128           // codes per smem chunk
#define NHALF 8192          // codes per grid.y slice
#define NCHUNKS (NHALF/CHUNK)   // 64

typedef unsigned long long u64;

// Scratch (__device__ globals; no allocations)
__device__ float g_e[NN*DD];                 // normalized codebook fp32
__device__ float g_z[P*DD];                  // normalized queries fp32
__device__ __nv_bfloat16 g_es[NN*64];        // [eh(32)|el(32)] per code (128B rows)
__device__ __nv_bfloat16 g_zs[P*64];         // [zh(32)|zl(32)] per position
__device__ int   g_cand[P*4];                // top-2 x 2 halves candidate indices
__device__ int   g_idx[P];                   // final argmax
__device__ float g_s[P];                     // exact best sim
__device__ int   g_hist[NN];                 // usage histogram

#define SW128(o) ((o) ^ (((o) >> 3) & 0x70))

__device__ __forceinline__ uint32_t smem_u32(const void* p) {
    uint32_t a;
    asm("{ .reg .u64 t; cvta.to.shared.u64 t, %1; cvt.u32.u64 %0, t; }" : "=r"(a) : "l"(p));
    return a;
}

// ---------------------------------------------------------------- init
__global__ void k_init() {
    int i = blockIdx.x * blockDim.x + threadIdx.x;
    if (i < NN) g_hist[i] = 0;
}

// ---------------------------------------------------------------- normalize codebook + bf16 split
__global__ void k_norm_emb(const float* __restrict__ emb) {
    int r = blockIdx.x * blockDim.x + threadIdx.x;
    if (r >= NN) return;
    const float4* src = (const float4*)(emb + r * DD);
    float v[DD];
    float sum = 0.f;
#pragma unroll
    for (int q = 0; q < 8; q++) {
        float4 t = src[q];
        v[4*q] = t.x; v[4*q+1] = t.y; v[4*q+2] = t.z; v[4*q+3] = t.w;
        sum += t.x*t.x + t.y*t.y + t.z*t.z + t.w*t.w;
    }
    float inv = 1.f / fmaxf(sqrtf(sum), 1e-6f);
    float* dst = g_e + r * DD;
    __nv_bfloat16* sd = g_es + r * 64;
#pragma unroll
    for (int d = 0; d < DD; d++) {
        float x = v[d] * inv;
        dst[d] = x;
        __nv_bfloat16 hi = __float2bfloat16(x);
        float res = x - __bfloat162float(hi);
        sd[d] = hi;
        sd[32 + d] = __float2bfloat16(res);
    }
}

// ---------------------------------------------------------------- project + normalize z + bf16 split
__global__ void k_project(const float* __restrict__ enc,
                          const float* __restrict__ proj_w,   // [D][C]
                          const float* __restrict__ proj_b) { // [D]
    __shared__ float ws[256 * DD];
    int tid = threadIdx.x;
    int p = blockIdx.x * 128 + tid;
    int b = p >> 10;
    int hw = p & 1023;
    const float* encp = enc + (b * CC) * HW + hw;

    float acc[DD];
#pragma unroll
    for (int d = 0; d < DD; d++) acc[d] = 0.f;

    for (int chunk = 0; chunk < 2; chunk++) {
        int c0 = chunk * 256;
        __syncthreads();
        for (int i = tid; i < 256 * DD; i += 128) {
            int ccl = i >> 5, d = i & 31;
            ws[i] = proj_w[d * CC + c0 + ccl];
        }
        __syncthreads();
        for (int ccl = 0; ccl < 256; ccl++) {
            float ev = encp[(c0 + ccl) * HW];
            const float4* wp = (const float4*)(ws + ccl * DD);
#pragma unroll
            for (int q = 0; q < 8; q++) {
                float4 w4 = wp[q];
                acc[4*q]   += ev * w4.x;
                acc[4*q+1] += ev * w4.y;
                acc[4*q+2] += ev * w4.z;
                acc[4*q+3] += ev * w4.w;
            }
        }
    }
    float sum = 0.f;
#pragma unroll
    for (int d = 0; d < DD; d++) {
        acc[d] += proj_b[d];
        sum += acc[d] * acc[d];
    }
    float inv = 1.f / fmaxf(sqrtf(sum), 1e-6f);
    float* dst = g_z + p * DD;
    __nv_bfloat16* sd = g_zs + p * 64;
#pragma unroll
    for (int d = 0; d < DD; d++) {
        float x = acc[d] * inv;
        dst[d] = x;
        __nv_bfloat16 hi = __float2bfloat16(x);
        float res = x - __bfloat162float(hi);
        sd[d] = hi;
        sd[32 + d] = __float2bfloat16(res);
    }
}

// ---------------------------------------------------------------- mma.sync search
// CTA: 128 threads / 4 warps, 128 positions; grid (P/128, 2) over code halves.
// A = [zh|zl] per position (K=64 bf16); B chunked 128 codes (K=64 bf16 rows).
// Per 8-code n-tile: 4 ldmatrix.x2 (b[s]) + 16 mma.m16n8k16 accumulating
// pass1 A[s]*B[s] (zh.eh+zl.el) and pass2 A[s]*B[(s+2)&3] (zh.el+zl.eh)
// into fp32 frags == exact-split fp32 sims. Top-2 tracked, exact rescore later.
__global__ void __launch_bounds__(128) k_search_mma() {
    __shared__ __align__(128) char sBuf0[16384];   // B buffer 0
    __shared__ __align__(128) char sBuf1[16384];   // A staging, then B buffer 1
    int tid = threadIdx.x, wid = tid >> 5, lane = tid & 31;
    int pbase = blockIdx.x * MTILE;
    int codebase0 = blockIdx.y * NHALF;
    uint32_t sb0 = smem_u32(sBuf0);
    uint32_t sb1 = smem_u32(sBuf1);

    // ---- stage A (128 x 128B) into sBuf1, swizzled ----
    {
        const uint4* asrc = (const uint4*)((const char*)g_zs + (size_t)pbase * 128);
        for (int i = tid; i < 1024; i += 128)
            *(uint4*)(sBuf1 + SW128(i * 16)) = asrc[i];
    }
    __syncthreads();

    // ---- load A fragments: afr[mtile][kstep][4] ----
    uint32_t afr[2][4][4];
#pragma unroll
    for (int mt = 0; mt < 2; mt++) {
#pragma unroll
        for (int s = 0; s < 4; s++) {
            int row = (lane & 15) + mt * 16 + wid * 32;
            int colb = ((lane >> 4) << 4) + s * 32;
            uint32_t addr = sb1 + SW128(row * 128 + colb);
            asm volatile("ldmatrix.sync.aligned.m8n8.x4.shared.b16 {%0,%1,%2,%3}, [%4];"
                : "=r"(afr[mt][s][0]), "=r"(afr[mt][s][1]),
                  "=r"(afr[mt][s][2]), "=r"(afr[mt][s][3]) : "r"(addr));
        }
    }
    __syncthreads();   // sBuf1 free for reuse as B buffer 1

    // top-2 state: slot = mt*2 + rowhalf
    float tv1[4], tv2[4];
    int ti1[4], ti2[4];
#pragma unroll
    for (int s = 0; s < 4; s++) { tv1[s] = -1e30f; tv2[s] = -1e30f; ti1[s] = 0; ti2[s] = 0; }

    // ---- cp.async staging helper ----
    // stage chunk c into buffer parity (c&1): 0->sBuf0, 1->sBuf1
#define STAGE_CHUNK(c) do { \
        const char* _src = (const char*)g_es + (size_t)(codebase0 + (c) * CHUNK) * 128; \
        uint32_t _dstb = ((c) & 1) ? sb1 : sb0; \
        for (int _i = tid; _i < 1024; _i += 128) { \
            uint32_t _d = _dstb + SW128(_i * 16); \
            asm volatile("cp.async.cg.shared.global [%0], [%1], 16;" \
                :: "r"(_d), "l"(_src + _i * 16) : "memory"); \
        } \
        asm volatile("cp.async.commit_group;" ::: "memory"); \
    } while (0)

    STAGE_CHUNK(0);

    for (int c = 0; c < NCHUNKS; c++) {
        if (c + 1 < NCHUNKS) {
            STAGE_CHUNK(c + 1);
            asm volatile("cp.async.wait_group 1;" ::: "memory");
        } else {
            asm volatile("cp.async.wait_group 0;" ::: "memory");
        }
        __syncthreads();

        uint32_t sbB = (c & 1) ? sb1 : sb0;
        int cbase = codebase0 + c * CHUNK;
        int li = lane & 15;

#pragma unroll 2
        for (int nt = 0; nt < CHUNK / 8; nt++) {
            // B fragments for 4 k-steps
            uint32_t bfr[4][2];
#pragma unroll
            for (int s = 0; s < 4; s++) {
                int code = nt * 8 + (li & 7);
                int koff = s * 32 + ((li & 8) ? 16 : 0);
                uint32_t addr = sbB + SW128(code * 128 + koff);
                asm volatile("ldmatrix.sync.aligned.m8n8.x2.shared.b16 {%0,%1}, [%2];"
                    : "=r"(bfr[s][0]), "=r"(bfr[s][1]) : "r"(addr));
            }
            float d0[2][4];
#pragma unroll
            for (int mt = 0; mt < 2; mt++) {
                d0[mt][0] = 0.f; d0[mt][1] = 0.f; d0[mt][2] = 0.f; d0[mt][3] = 0.f;
#pragma unroll
                for (int s = 0; s < 4; s++) {
                    asm volatile(
                        "mma.sync.aligned.m16n8k16.row.col.f32.bf16.bf16.f32 "
                        "{%0,%1,%2,%3}, {%4,%5,%6,%7}, {%8,%9}, {%0,%1,%2,%3};"
                        : "+f"(d0[mt][0]), "+f"(d0[mt][1]), "+f"(d0[mt][2]), "+f"(d0[mt][3])
                        : "r"(afr[mt][s][0]), "r"(afr[mt][s][1]), "r"(afr[mt][s][2]), "r"(afr[mt][s][3]),
                          "r"(bfr[s][0]), "r"(bfr[s][1]));
                }
#pragma unroll
                for (int s = 0; s < 4; s++) {
                    int bs = (s + 2) & 3;
                    asm volatile(
                        "mma.sync.aligned.m16n8k16.row.col.f32.bf16.bf16.f32 "
                        "{%0,%1,%2,%3}, {%4,%5,%6,%7}, {%8,%9}, {%0,%1,%2,%3};"
                        : "+f"(d0[mt][0]), "+f"(d0[mt][1]), "+f"(d0[mt][2]), "+f"(d0[mt][3])
                        : "r"(afr[mt][s][0]), "r"(afr[mt][s][1]), "r"(afr[mt][s][2]), "r"(afr[mt][s][3]),
                          "r"(bfr[bs][0]), "r"(bfr[bs][1]));
                }
            }
            // top-2 update (ties keep earlier = lower index)
            int nb = cbase + nt * 8 + 2 * (lane & 3);
#pragma unroll
            for (int mt = 0; mt < 2; mt++) {
#pragma unroll
                for (int h = 0; h < 2; h++) {
                    int slot = mt * 2 + h;
#pragma unroll
                    for (int e = 0; e < 2; e++) {
                        float v = d0[mt][h * 2 + e];
                        int idx = nb + e;
                        if (v > tv1[slot]) {
                            tv2[slot] = tv1[slot]; ti2[slot] = ti1[slot];
                            tv1[slot] = v; ti1[slot] = idx;
                        } else if (v > tv2[slot]) {
                            tv2[slot] = v; ti2[slot] = idx;
                        }
                    }
                }
            }
        }
        __syncthreads();   // all warps done reading buffer before it is restaged
    }

    // ---- merge top-2 across the 4 lanes sharing each row ----
#pragma unroll
    for (int slot = 0; slot < 4; slot++) {
#pragma unroll
        for (int off = 1; off <= 2; off <<= 1) {
            float ov1 = __shfl_xor_sync(0xFFFFFFFFu, tv1[slot], off);
            int   oi1 = __shfl_xor_sync(0xFFFFFFFFu, ti1[slot], off);
            float ov2 = __shfl_xor_sync(0xFFFFFFFFu, tv2[slot], off);
            int   oi2 = __shfl_xor_sync(0xFFFFFFFFu, ti2[slot], off);
            bool o1beats = (ov1 > tv1[slot]) || (ov1 == tv1[slot] && oi1 < ti1[slot]);
            if (o1beats) {
                float nv2; int ni2;
                if (tv1[slot] > ov2 || (tv1[slot] == ov2 && ti1[slot] < oi2)) { nv2 = tv1[slot]; ni2 = ti1[slot]; }
                else { nv2 = ov2; ni2 = oi2; }
                tv1[slot] = ov1; ti1[slot] = oi1;
                tv2[slot] = nv2; ti2[slot] = ni2;
            } else {
                if (ov1 > tv2[slot] || (ov1 == tv2[slot] && oi1 < ti2[slot])) { tv2[slot] = ov1; ti2[slot] = oi1; }
            }
        }
    }
    if ((lane & 3) == 0) {
#pragma unroll
        for (int slot = 0; slot < 4; slot++) {
            int mt = slot >> 1, h = slot & 1;
            int p = pbase + wid * 32 + mt * 16 + h * 8 + (lane >> 2);
            g_cand[p * 4 + blockIdx.y * 2]     = ti1[slot];
            g_cand[p * 4 + blockIdx.y * 2 + 1] = ti2[slot];
        }
    }
#undef STAGE_CHUNK
}

// ---------------------------------------------------------------- finalize: exact rescore of 4 candidates
__global__ void k_finalize() {
    int p = blockIdx.x * blockDim.x + threadIdx.x;
    if (p >= P) return;
    const float* z = g_z + p * DD;
    float bs = -1e30f;
    int bi = 0x7FFFFFFF;
#pragma unroll
    for (int c = 0; c < 4; c++) {
        int idx = g_cand[p * 4 + c];
        const float* e = g_e + idx * DD;
        float s = 0.f;
#pragma unroll
        for (int d = 0; d < DD; d++) s += z[d] * e[d];
        if (s > bs || (s == bs && idx < bi)) { bs = s; bi = idx; }
    }
    g_idx[p] = bi;
    g_s[p] = bs;
    atomicAdd(&g_hist[bi], 1);
}

// ---------------------------------------------------------------- output GEMM (fp32 scalar, f32x2)
__device__ __forceinline__ u64 fma2(u64 a, u64 b, u64 c) {
    u64 d;
    asm("fma.rn.f32x2 %0, %1, %2, %3;" : "=l"(d) : "l"(a), "l"(b), "l"(c));
    return d;
}
__device__ __forceinline__ u64 add2(u64 a, u64 b) {
    u64 d;
    asm("add.rn.f32x2 %0, %1, %2;" : "=l"(d) : "l"(a), "l"(b));
    return d;
}
__device__ __forceinline__ float hsum2(u64 a) {
    unsigned lo, hi;
    asm("mov.b64 {%0, %1}, %2;" : "=r"(lo), "=r"(hi) : "l"(a));
    return __uint_as_float(lo) + __uint_as_float(hi);
}

__global__ void k_output(const float* __restrict__ exp_w,   // [C][D]
                         const float* __restrict__ exp_b,   // [C]
                         float* __restrict__ out) {
    __shared__ float ws[128 * DD];
    __shared__ float wb[128];
    int tid = threadIdx.x;
    int p = blockIdx.x * 128 + tid;
    int b = p >> 10;
    int hw = p & 1023;

    ulonglong2 cz[8];
    {
        int idx = g_idx[p];
        const ulonglong2* cp = (const ulonglong2*)(g_e + idx * DD);
#pragma unroll
        for (int q = 0; q < 8; q++) cz[q] = cp[q];
    }
    float* outp = out + (b * CC) * HW + hw;

    for (int chunk = 0; chunk < 4; chunk++) {
        int c0 = chunk * 128;
        __syncthreads();
        for (int i = tid; i < 128 * DD; i += 128) ws[i] = exp_w[c0 * DD + i];
        wb[tid] = exp_b[c0 + tid];
        __syncthreads();
        for (int ccl = 0; ccl < 128; ccl++) {
            const ulonglong2* wp = (const ulonglong2*)(ws + ccl * DD);
            u64 a0 = 0ull, a1 = 0ull, a2 = 0ull, a3 = 0ull;
#pragma unroll
            for (int q = 0; q < 8; q += 2) {
                ulonglong2 w0 = wp[q];
                ulonglong2 w1 = wp[q + 1];
                a0 = fma2(w0.x, cz[q].x, a0);
                a1 = fma2(w0.y, cz[q].y, a1);
                a2 = fma2(w1.x, cz[q + 1].x, a2);
                a3 = fma2(w1.y, cz[q + 1].y, a3);
            }
            a0 = add2(a0, a1);
            a2 = add2(a2, a3);
            a0 = add2(a0, a2);
            outp[(c0 + ccl) * HW] = hsum2(a0) + wb[ccl];
        }
    }
}

// ---------------------------------------------------------------- scalars
__global__ void k_scalars(float* __restrict__ out) {
    __shared__ float red[256];
    int tid = threadIdx.x;

    float ls = 0.f;
    for (int i = tid; i < P; i += 256) ls += g_s[i];
    red[tid] = ls;
    __syncthreads();
    for (int off = 128; off > 0; off >>= 1) {
        if (tid < off) red[tid] += red[tid + off];
        __syncthreads();
    }
    float sum_s = red[0];
    __syncthreads();

    float hs = 0.f;
    const float invP = 1.0f / (float)P;
    for (int i = tid; i < NN; i += 256) {
        float u = (float)g_hist[i] * invP;
        hs += -u * logf(u + 1e-6f);
    }
    red[tid] = hs;
    __syncthreads();
    for (int off = 128; off > 0; off >>= 1) {
        if (tid < off) red[tid] += red[tid + off];
        __syncthreads();
    }
    if (tid == 0) {
        out[OUT_ELEMS]     = (2.f * (float)P - 2.f * sum_s) / ((float)P * (float)DD);
        out[OUT_ELEMS + 1] = expf(red[0]);
    }
}

// ---------------------------------------------------------------- launch
extern "C" void kernel_launch(void* const* d_in, const int* in_sizes, int n_in,
                              void* d_out, int out_size) {
    const float* encodings = (const float*)d_in[0];
    const float* emb_weight = (const float*)d_in[1];
    const float* proj_w = (const float*)d_in[2];
    const float* proj_b = (const float*)d_in[3];
    const float* exp_w = (const float*)d_in[4];
    const float* exp_b = (const float*)d_in[5];
    float* out = (float*)d_out;

    k_init<<<NN / 256, 256>>>();
    k_norm_emb<<<NN / 128, 128>>>(emb_weight);
    k_project<<<P / 128, 128>>>(encodings, proj_w, proj_b);
    k_search_mma<<<dim3(P / MTILE, 2), 128>>>();
    k_finalize<<<P / 256, 256>>>();
    k_output<<<P / 128, 128>>>(exp_w, exp_b, out);
    k_scalars<<<1, 256>>>(out);
}

// round 12
// speedup vs baseline: 1.2212x; 1.2212x over previous
#include <cuda_runtime.h>
#include <cuda_bf16.h>
#include <math.h>
#include <stdint.h>

// Problem constants
#define BB 16
#define CC 512
#define HW 1024
#define P  16384            // positions
#define NN 16384            // codebook size
#define DD 32               // embedding dim
#define OUT_ELEMS (BB*CC*HW)

#define MTILE 128           // positions per CTA
#define CHUNK 128           // codes per smem chunk
#define NSPLITY 8           // grid.y code slices
#define NHALF (NN/NSPLITY)  // 2048 codes per slice
#define NCHUNKS (NHALF/CHUNK)   // 16

typedef unsigned long long u64;

// Scratch (__device__ globals; no allocations)
__device__ float g_e[NN*DD];                 // normalized codebook fp32
__device__ float g_z[P*DD];                  // normalized queries fp32
__device__ __nv_bfloat16 g_es[NN*64];        // [eh(32)|el(32)] per code (128B rows)
__device__ __nv_bfloat16 g_zs[P*64];         // [zh(32)|zl(32)] per position
__device__ int   g_cand[P*2*NSPLITY];        // top-2 per slice candidate indices
__device__ int   g_idx[P];                   // final argmax
__device__ float g_s[P];                     // exact best sim
__device__ int   g_hist[NN];                 // usage histogram

#define SW128(o) ((o) ^ (((o) >> 3) & 0x70))

__device__ __forceinline__ uint32_t smem_u32(const void* p) {
    uint32_t a;
    asm("{ .reg .u64 t; cvta.to.shared.u64 t, %1; cvt.u32.u64 %0, t; }" : "=r"(a) : "l"(p));
    return a;
}

// ---------------------------------------------------------------- init
__global__ void k_init() {
    int i = blockIdx.x * blockDim.x + threadIdx.x;
    if (i < NN) g_hist[i] = 0;
}

// ---------------------------------------------------------------- normalize codebook + bf16 split
__global__ void k_norm_emb(const float* __restrict__ emb) {
    int r = blockIdx.x * blockDim.x + threadIdx.x;
    if (r >= NN) return;
    const float4* src = (const float4*)(emb + r * DD);
    float v[DD];
    float sum = 0.f;
#pragma unroll
    for (int q = 0; q < 8; q++) {
        float4 t = src[q];
        v[4*q] = t.x; v[4*q+1] = t.y; v[4*q+2] = t.z; v[4*q+3] = t.w;
        sum += t.x*t.x + t.y*t.y + t.z*t.z + t.w*t.w;
    }
    float inv = 1.f / fmaxf(sqrtf(sum), 1e-6f);
    float* dst = g_e + r * DD;
    __nv_bfloat16* sd = g_es + r * 64;
#pragma unroll
    for (int d = 0; d < DD; d++) {
        float x = v[d] * inv;
        dst[d] = x;
        __nv_bfloat16 hi = __float2bfloat16(x);
        float res = x - __bfloat162float(hi);
        sd[d] = hi;
        sd[32 + d] = __float2bfloat16(res);
    }
}

// ---------------------------------------------------------------- project + normalize z + bf16 split
__global__ void k_project(const float* __restrict__ enc,
                          const float* __restrict__ proj_w,   // [D][C]
                          const float* __restrict__ proj_b) { // [D]
    __shared__ float ws[256 * DD];
    int tid = threadIdx.x;
    int p = blockIdx.x * 128 + tid;
    int b = p >> 10;
    int hw = p & 1023;
    const float* encp = enc + (b * CC) * HW + hw;

    float acc[DD];
#pragma unroll
    for (int d = 0; d < DD; d++) acc[d] = 0.f;

    for (int chunk = 0; chunk < 2; chunk++) {
        int c0 = chunk * 256;
        __syncthreads();
        for (int i = tid; i < 256 * DD; i += 128) {
            int ccl = i >> 5, d = i & 31;
            ws[i] = proj_w[d * CC + c0 + ccl];
        }
        __syncthreads();
        for (int ccl = 0; ccl < 256; ccl++) {
            float ev = encp[(c0 + ccl) * HW];
            const float4* wp = (const float4*)(ws + ccl * DD);
#pragma unroll
            for (int q = 0; q < 8; q++) {
                float4 w4 = wp[q];
                acc[4*q]   += ev * w4.x;
                acc[4*q+1] += ev * w4.y;
                acc[4*q+2] += ev * w4.z;
                acc[4*q+3] += ev * w4.w;
            }
        }
    }
    float sum = 0.f;
#pragma unroll
    for (int d = 0; d < DD; d++) {
        acc[d] += proj_b[d];
        sum += acc[d] * acc[d];
    }
    float inv = 1.f / fmaxf(sqrtf(sum), 1e-6f);
    float* dst = g_z + p * DD;
    __nv_bfloat16* sd = g_zs + p * 64;
#pragma unroll
    for (int d = 0; d < DD; d++) {
        float x = acc[d] * inv;
        dst[d] = x;
        __nv_bfloat16 hi = __float2bfloat16(x);
        float res = x - __bfloat162float(hi);
        sd[d] = hi;
        sd[32 + d] = __float2bfloat16(res);
    }
}

// ---------------------------------------------------------------- mma.sync search
// CTA: 128 threads / 4 warps, 128 positions; grid (P/128, NSPLITY) code slices.
// Per 8-code n-tile: 2 ldmatrix.x4 (B, 4 k-steps) + 16 mma.m16n8k16:
// pass1 A[s]*B[s] (zh.eh+zl.el), pass2 A[s]*B[(s+2)&3] (zh.el+zl.eh)
// -> exact fp32-split sims. Top-2 per slice tracked; exact rescore later.
__global__ void __launch_bounds__(128) k_search_mma() {
    __shared__ __align__(128) char sBuf0[16384];   // B buffer 0
    __shared__ __align__(128) char sBuf1[16384];   // A staging, then B buffer 1
    int tid = threadIdx.x, wid = tid >> 5, lane = tid & 31;
    int pbase = blockIdx.x * MTILE;
    int codebase0 = blockIdx.y * NHALF;
    uint32_t sb0 = smem_u32(sBuf0);
    uint32_t sb1 = smem_u32(sBuf1);

    // ---- stage A (128 x 128B) into sBuf1, swizzled ----
    {
        const uint4* asrc = (const uint4*)((const char*)g_zs + (size_t)pbase * 128);
        for (int i = tid; i < 1024; i += 128)
            *(uint4*)(sBuf1 + SW128(i * 16)) = asrc[i];
    }
    __syncthreads();

    // ---- load A fragments: afr[mtile][kstep][4] ----
    uint32_t afr[2][4][4];
#pragma unroll
    for (int mt = 0; mt < 2; mt++) {
#pragma unroll
        for (int s = 0; s < 4; s++) {
            int row = (lane & 15) + mt * 16 + wid * 32;
            int colb = ((lane >> 4) << 4) + s * 32;
            uint32_t addr = sb1 + SW128(row * 128 + colb);
            asm volatile("ldmatrix.sync.aligned.m8n8.x4.shared.b16 {%0,%1,%2,%3}, [%4];"
                : "=r"(afr[mt][s][0]), "=r"(afr[mt][s][1]),
                  "=r"(afr[mt][s][2]), "=r"(afr[mt][s][3]) : "r"(addr));
        }
    }
    __syncthreads();   // sBuf1 free for reuse as B buffer 1

    // top-2 state: slot = mt*2 + rowhalf
    float tv1[4], tv2[4];
    int ti1[4], ti2[4];
#pragma unroll
    for (int s = 0; s < 4; s++) { tv1[s] = -1e30f; tv2[s] = -1e30f; ti1[s] = 0; ti2[s] = 0; }

    // ---- cp.async staging: chunk c -> buffer (c&1) ----
#define STAGE_CHUNK(c) do { \
        const char* _src = (const char*)g_es + (size_t)(codebase0 + (c) * CHUNK) * 128; \
        uint32_t _dstb = ((c) & 1) ? sb1 : sb0; \
        for (int _i = tid; _i < 1024; _i += 128) { \
            uint32_t _d = _dstb + SW128(_i * 16); \
            asm volatile("cp.async.cg.shared.global [%0], [%1], 16;" \
                :: "r"(_d), "l"(_src + _i * 16) : "memory"); \
        } \
        asm volatile("cp.async.commit_group;" ::: "memory"); \
    } while (0)

    STAGE_CHUNK(0);

    // B ldmatrix.x4 lane addressing: matrix m = lane>>3 covers (s = m>>1, khalf = m&1)
    // code = nt*8 + (lane&7); koff = (m>>1)*32 + (m&1)*16
    int bcode = lane & 7;
    int bko = ((lane >> 4) << 5) + (((lane >> 3) & 1) << 4);

    for (int c = 0; c < NCHUNKS; c++) {
        if (c + 1 < NCHUNKS) {
            STAGE_CHUNK(c + 1);
            asm volatile("cp.async.wait_group 1;" ::: "memory");
        } else {
            asm volatile("cp.async.wait_group 0;" ::: "memory");
        }
        __syncthreads();

        uint32_t sbB = (c & 1) ? sb1 : sb0;
        int cbase = codebase0 + c * CHUNK;

#pragma unroll 2
        for (int nt = 0; nt < CHUNK / 8; nt++) {
            // B fragments: two x4 loads cover all 4 k-steps
            uint32_t bfr[4][2];
            {
                uint32_t a0 = sbB + SW128((nt * 8 + bcode) * 128 + bko);
                asm volatile("ldmatrix.sync.aligned.m8n8.x4.shared.b16 {%0,%1,%2,%3}, [%4];"
                    : "=r"(bfr[0][0]), "=r"(bfr[0][1]), "=r"(bfr[1][0]), "=r"(bfr[1][1]) : "r"(a0));
                uint32_t a1 = sbB + SW128((nt * 8 + bcode) * 128 + bko + 64);
                asm volatile("ldmatrix.sync.aligned.m8n8.x4.shared.b16 {%0,%1,%2,%3}, [%4];"
                    : "=r"(bfr[2][0]), "=r"(bfr[2][1]), "=r"(bfr[3][0]), "=r"(bfr[3][1]) : "r"(a1));
            }
            float d0[2][4];
#pragma unroll
            for (int mt = 0; mt < 2; mt++) {
                d0[mt][0] = 0.f; d0[mt][1] = 0.f; d0[mt][2] = 0.f; d0[mt][3] = 0.f;
#pragma unroll
                for (int s = 0; s < 4; s++) {
                    asm volatile(
                        "mma.sync.aligned.m16n8k16.row.col.f32.bf16.bf16.f32 "
                        "{%0,%1,%2,%3}, {%4,%5,%6,%7}, {%8,%9}, {%0,%1,%2,%3};"
                        : "+f"(d0[mt][0]), "+f"(d0[mt][1]), "+f"(d0[mt][2]), "+f"(d0[mt][3])
                        : "r"(afr[mt][s][0]), "r"(afr[mt][s][1]), "r"(afr[mt][s][2]), "r"(afr[mt][s][3]),
                          "r"(bfr[s][0]), "r"(bfr[s][1]));
                }
#pragma unroll
                for (int s = 0; s < 4; s++) {
                    int bs = (s + 2) & 3;
                    asm volatile(
                        "mma.sync.aligned.m16n8k16.row.col.f32.bf16.bf16.f32 "
                        "{%0,%1,%2,%3}, {%4,%5,%6,%7}, {%8,%9}, {%0,%1,%2,%3};"
                        : "+f"(d0[mt][0]), "+f"(d0[mt][1]), "+f"(d0[mt][2]), "+f"(d0[mt][3])
                        : "r"(afr[mt][s][0]), "r"(afr[mt][s][1]), "r"(afr[mt][s][2]), "r"(afr[mt][s][3]),
                          "r"(bfr[bs][0]), "r"(bfr[bs][1]));
                }
            }
            // top-2 update (ties keep earlier = lower index)
            int nb = cbase + nt * 8 + 2 * (lane & 3);
#pragma unroll
            for (int mt = 0; mt < 2; mt++) {
#pragma unroll
                for (int h = 0; h < 2; h++) {
                    int slot = mt * 2 + h;
#pragma unroll
                    for (int e = 0; e < 2; e++) {
                        float v = d0[mt][h * 2 + e];
                        int idx = nb + e;
                        if (v > tv1[slot]) {
                            tv2[slot] = tv1[slot]; ti2[slot] = ti1[slot];
                            tv1[slot] = v; ti1[slot] = idx;
                        } else if (v > tv2[slot]) {
                            tv2[slot] = v; ti2[slot] = idx;
                        }
                    }
                }
            }
        }
        __syncthreads();   // all warps done reading buffer before it is restaged
    }

    // ---- merge top-2 across the 4 lanes sharing each row ----
#pragma unroll
    for (int slot = 0; slot < 4; slot++) {
#pragma unroll
        for (int off = 1; off <= 2; off <<= 1) {
            float ov1 = __shfl_xor_sync(0xFFFFFFFFu, tv1[slot], off);
            int   oi1 = __shfl_xor_sync(0xFFFFFFFFu, ti1[slot], off);
            float ov2 = __shfl_xor_sync(0xFFFFFFFFu, tv2[slot], off);
            int   oi2 = __shfl_xor_sync(0xFFFFFFFFu, ti2[slot], off);
            bool o1beats = (ov1 > tv1[slot]) || (ov1 == tv1[slot] && oi1 < ti1[slot]);
            if (o1beats) {
                float nv2; int ni2;
                if (tv1[slot] > ov2 || (tv1[slot] == ov2 && ti1[slot] < oi2)) { nv2 = tv1[slot]; ni2 = ti1[slot]; }
                else { nv2 = ov2; ni2 = oi2; }
                tv1[slot] = ov1; ti1[slot] = oi1;
                tv2[slot] = nv2; ti2[slot] = ni2;
            } else {
                if (ov1 > tv2[slot] || (ov1 == tv2[slot] && oi1 < ti2[slot])) { tv2[slot] = ov1; ti2[slot] = oi1; }
            }
        }
    }
    if ((lane & 3) == 0) {
#pragma unroll
        for (int slot = 0; slot < 4; slot++) {
            int mt = slot >> 1, h = slot & 1;
            int p = pbase + wid * 32 + mt * 16 + h * 8 + (lane >> 2);
            g_cand[p * (2 * NSPLITY) + blockIdx.y * 2]     = ti1[slot];
            g_cand[p * (2 * NSPLITY) + blockIdx.y * 2 + 1] = ti2[slot];
        }
    }
#undef STAGE_CHUNK
}

// ---------------------------------------------------------------- finalize: exact rescore of 2*NSPLITY candidates
__global__ void k_finalize() {
    int p = blockIdx.x * blockDim.x + threadIdx.x;
    if (p >= P) return;
    float z[DD];
#pragma unroll
    for (int d = 0; d < DD; d++) z[d] = g_z[p * DD + d];
    float bs = -1e30f;
    int bi = 0x7FFFFFFF;
#pragma unroll 4
    for (int c = 0; c < 2 * NSPLITY; c++) {
        int idx = g_cand[p * (2 * NSPLITY) + c];
        const float* e = g_e + idx * DD;
        float s = 0.f;
#pragma unroll
        for (int d = 0; d < DD; d++) s += z[d] * e[d];
        if (s > bs || (s == bs && idx < bi)) { bs = s; bi = idx; }
    }
    g_idx[p] = bi;
    g_s[p] = bs;
    atomicAdd(&g_hist[bi], 1);
}

// ---------------------------------------------------------------- output GEMM (fp32 scalar, f32x2)
__device__ __forceinline__ u64 fma2(u64 a, u64 b, u64 c) {
    u64 d;
    asm("fma.rn.f32x2 %0, %1, %2, %3;" : "=l"(d) : "l"(a), "l"(b), "l"(c));
    return d;
}
__device__ __forceinline__ u64 add2(u64 a, u64 b) {
    u64 d;
    asm("add.rn.f32x2 %0, %1, %2;" : "=l"(d) : "l"(a), "l"(b));
    return d;
}
__device__ __forceinline__ float hsum2(u64 a) {
    unsigned lo, hi;
    asm("mov.b64 {%0, %1}, %2;" : "=r"(lo), "=r"(hi) : "l"(a));
    return __uint_as_float(lo) + __uint_as_float(hi);
}

__global__ void k_output(const float* __restrict__ exp_w,   // [C][D]
                         const float* __restrict__ exp_b,   // [C]
                         float* __restrict__ out) {
    __shared__ float ws[128 * DD];
    __shared__ float wb[128];
    int tid = threadIdx.x;
    int p = blockIdx.x * 128 + tid;
    int b = p >> 10;
    int hw = p & 1023;

    ulonglong2 cz[8];
    {
        int idx = g_idx[p];
        const ulonglong2* cp = (const ulonglong2*)(g_e + idx * DD);
#pragma unroll
        for (int q = 0; q < 8; q++) cz[q] = cp[q];
    }
    float* outp = out + (b * CC) * HW + hw;

    for (int chunk = 0; chunk < 4; chunk++) {
        int c0 = chunk * 128;
        __syncthreads();
        for (int i = tid; i < 128 * DD; i += 128) ws[i] = exp_w[c0 * DD + i];
        wb[tid] = exp_b[c0 + tid];
        __syncthreads();
        for (int ccl = 0; ccl < 128; ccl++) {
            const ulonglong2* wp = (const ulonglong2*)(ws + ccl * DD);
            u64 a0 = 0ull, a1 = 0ull, a2 = 0ull, a3 = 0ull;
#pragma unroll
            for (int q = 0; q < 8; q += 2) {
                ulonglong2 w0 = wp[q];
                ulonglong2 w1 = wp[q + 1];
                a0 = fma2(w0.x, cz[q].x, a0);
                a1 = fma2(w0.y, cz[q].y, a1);
                a2 = fma2(w1.x, cz[q + 1].x, a2);
                a3 = fma2(w1.y, cz[q + 1].y, a3);
            }
            a0 = add2(a0, a1);
            a2 = add2(a2, a3);
            a0 = add2(a0, a2);
            outp[(c0 + ccl) * HW] = hsum2(a0) + wb[ccl];
        }
    }
}

// ---------------------------------------------------------------- scalars
__global__ void k_scalars(float* __restrict__ out) {
    __shared__ float red[256];
    int tid = threadIdx.x;

    float ls = 0.f;
    for (int i = tid; i < P; i += 256) ls += g_s[i];
    red[tid] = ls;
    __syncthreads();
    for (int off = 128; off > 0; off >>= 1) {
        if (tid < off) red[tid] += red[tid + off];
        __syncthreads();
    }
    float sum_s = red[0];
    __syncthreads();

    float hs = 0.f;
    const float invP = 1.0f / (float)P;
    for (int i = tid; i < NN; i += 256) {
        float u = (float)g_hist[i] * invP;
        hs += -u * logf(u + 1e-6f);
    }
    red[tid] = hs;
    __syncthreads();
    for (int off = 128; off > 0; off >>= 1) {
        if (tid < off) red[tid] += red[tid + off];
        __syncthreads();
    }
    if (tid == 0) {
        out[OUT_ELEMS]     = (2.f * (float)P - 2.f * sum_s) / ((float)P * (float)DD);
        out[OUT_ELEMS + 1] = expf(red[0]);
    }
}

// ---------------------------------------------------------------- launch
extern "C" void kernel_launch(void* const* d_in, const int* in_sizes, int n_in,
                              void* d_out, int out_size) {
    const float* encodings = (const float*)d_in[0];
    const float* emb_weight = (const float*)d_in[1];
    const float* proj_w = (const float*)d_in[2];
    const float* proj_b = (const float*)d_in[3];
    const float* exp_w = (const float*)d_in[4];
    const float* exp_b = (const float*)d_in[5];
    float* out = (float*)d_out;

    k_init<<<NN / 256, 256>>>();
    k_norm_emb<<<NN / 128, 128>>>(emb_weight);
    k_project<<<P / 128, 128>>>(encodings, proj_w, proj_b);
    k_search_mma<<<dim3(P / MTILE, NSPLITY), 128>>>();
    k_finalize<<<P / 256, 256>>>();
    k_output<<<P / 128, 128>>>(exp_w, exp_b, out);
    k_scalars<<<1, 256>>>(out);
}

// round 15
// speedup vs baseline: 1.2324x; 1.0092x over previous
#include <cuda_runtime.h>
#include <cuda_bf16.h>
#include <math.h>
#include <stdint.h>

// Problem constants
#define BB 16
#define CC 512
#define HW 1024
#define P  16384            // positions
#define NN 16384            // codebook size
#define DD 32               // embedding dim
#define OUT_ELEMS (BB*CC*HW)

#define MTILE 128           // positions per CTA
#define CHUNK 128           // codes per smem chunk
#define NSPLITY 16          // grid.y code slices
#define NHALF (NN/NSPLITY)  // 1024 codes per slice
#define NCHUNKS (NHALF/CHUNK)   // 8
#define NCAND (2*NSPLITY)   // 32 candidates per position

typedef unsigned long long u64;

// Scratch (__device__ globals; no allocations)
__device__ float g_e[NN*DD];                 // normalized codebook fp32
__device__ float g_z[P*DD];                  // normalized queries fp32
__device__ __nv_bfloat16 g_es[NN*64];        // [eh(32)|el(32)] per code (128B rows)
__device__ __nv_bfloat16 g_zs[P*64];         // [zh(32)|zl(32)] per position
__device__ int   g_cand[P*NCAND];            // top-2 per slice candidate indices
__device__ int   g_idx[P];                   // final argmax
__device__ float g_s[P];                     // exact best sim
__device__ int   g_hist[NN];                 // usage histogram

#define SW128(o) ((o) ^ (((o) >> 3) & 0x70))

__device__ __forceinline__ uint32_t smem_u32(const void* p) {
    uint32_t a;
    asm("{ .reg .u64 t; cvta.to.shared.u64 t, %1; cvt.u32.u64 %0, t; }" : "=r"(a) : "l"(p));
    return a;
}

// ---------------------------------------------------------------- init
__global__ void k_init() {
    int i = blockIdx.x * blockDim.x + threadIdx.x;
    if (i < NN) g_hist[i] = 0;
}

// ---------------------------------------------------------------- normalize codebook + bf16 split
__global__ void k_norm_emb(const float* __restrict__ emb) {
    int r = blockIdx.x * blockDim.x + threadIdx.x;
    if (r >= NN) return;
    const float4* src = (const float4*)(emb + r * DD);
    float v[DD];
    float sum = 0.f;
#pragma unroll
    for (int q = 0; q < 8; q++) {
        float4 t = src[q];
        v[4*q] = t.x; v[4*q+1] = t.y; v[4*q+2] = t.z; v[4*q+3] = t.w;
        sum += t.x*t.x + t.y*t.y + t.z*t.z + t.w*t.w;
    }
    float inv = 1.f / fmaxf(sqrtf(sum), 1e-6f);
    float* dst = g_e + r * DD;
    __nv_bfloat16* sd = g_es + r * 64;
#pragma unroll
    for (int d = 0; d < DD; d++) {
        float x = v[d] * inv;
        dst[d] = x;
        __nv_bfloat16 hi = __float2bfloat16(x);
        float res = x - __bfloat162float(hi);
        sd[d] = hi;
        sd[32 + d] = __float2bfloat16(res);
    }
}

// ---------------------------------------------------------------- project + normalize z + bf16 split
__global__ void k_project(const float* __restrict__ enc,
                          const float* __restrict__ proj_w,   // [D][C]
                          const float* __restrict__ proj_b) { // [D]
    __shared__ float ws[256 * DD];
    int tid = threadIdx.x;
    int p = blockIdx.x * 128 + tid;
    int b = p >> 10;
    int hw = p & 1023;
    const float* encp = enc + (b * CC) * HW + hw;

    float acc[DD];
#pragma unroll
    for (int d = 0; d < DD; d++) acc[d] = 0.f;

    for (int chunk = 0; chunk < 2; chunk++) {
        int c0 = chunk * 256;
        __syncthreads();
        for (int i = tid; i < 256 * DD; i += 128) {
            int ccl = i >> 5, d = i & 31;
            ws[i] = proj_w[d * CC + c0 + ccl];
        }
        __syncthreads();
        for (int ccl = 0; ccl < 256; ccl++) {
            float ev = encp[(c0 + ccl) * HW];
            const float4* wp = (const float4*)(ws + ccl * DD);
#pragma unroll
            for (int q = 0; q < 8; q++) {
                float4 w4 = wp[q];
                acc[4*q]   += ev * w4.x;
                acc[4*q+1] += ev * w4.y;
                acc[4*q+2] += ev * w4.z;
                acc[4*q+3] += ev * w4.w;
            }
        }
    }
    float sum = 0.f;
#pragma unroll
    for (int d = 0; d < DD; d++) {
        acc[d] += proj_b[d];
        sum += acc[d] * acc[d];
    }
    float inv = 1.f / fmaxf(sqrtf(sum), 1e-6f);
    float* dst = g_z + p * DD;
    __nv_bfloat16* sd = g_zs + p * 64;
#pragma unroll
    for (int d = 0; d < DD; d++) {
        float x = acc[d] * inv;
        dst[d] = x;
        __nv_bfloat16 hi = __float2bfloat16(x);
        float res = x - __bfloat162float(hi);
        sd[d] = hi;
        sd[32 + d] = __float2bfloat16(res);
    }
}

// ---------------------------------------------------------------- mma.sync search
// CTA: 128 threads / 4 warps, 128 positions; grid (P/128, NSPLITY) code slices.
// Per 8-code n-tile: 2 ldmatrix.x4 (B) + 16 mma.m16n8k16 (split bf16, 4
// independent accumulation chains) + pairwise-max + lean top-2 epilogue.
__global__ void __launch_bounds__(128, 6) k_search_mma() {
    __shared__ __align__(128) char sBuf0[16384];   // B buffer 0
    __shared__ __align__(128) char sBuf1[16384];   // A staging, then B buffer 1
    int tid = threadIdx.x, wid = tid >> 5, lane = tid & 31;
    int pbase = blockIdx.x * MTILE;
    int codebase0 = blockIdx.y * NHALF;
    uint32_t sb0 = smem_u32(sBuf0);
    uint32_t sb1 = smem_u32(sBuf1);

    // ---- stage A (128 x 128B) into sBuf1, swizzled ----
    {
        const uint4* asrc = (const uint4*)((const char*)g_zs + (size_t)pbase * 128);
        for (int i = tid; i < 1024; i += 128)
            *(uint4*)(sBuf1 + SW128(i * 16)) = asrc[i];
    }
    __syncthreads();

    // ---- load A fragments: afr[mtile][kstep][4] ----
    uint32_t afr[2][4][4];
#pragma unroll
    for (int mt = 0; mt < 2; mt++) {
#pragma unroll
        for (int s = 0; s < 4; s++) {
            int row = (lane & 15) + mt * 16 + wid * 32;
            int colb = ((lane >> 4) << 4) + s * 32;
            uint32_t addr = sb1 + SW128(row * 128 + colb);
            asm volatile("ldmatrix.sync.aligned.m8n8.x4.shared.b16 {%0,%1,%2,%3}, [%4];"
                : "=r"(afr[mt][s][0]), "=r"(afr[mt][s][1]),
                  "=r"(afr[mt][s][2]), "=r"(afr[mt][s][3]) : "r"(addr));
        }
    }
    __syncthreads();   // sBuf1 free for reuse as B buffer 1

    // top-2 state: slot = mt*2 + rowhalf
    float tv1[4], tv2[4];
    int ti1[4], ti2[4];
#pragma unroll
    for (int s = 0; s < 4; s++) { tv1[s] = -1e30f; tv2[s] = -1e30f; ti1[s] = 0; ti2[s] = 0; }

    // ---- cp.async staging: chunk c -> buffer (c&1) ----
#define STAGE_CHUNK(c) do { \
        const char* _src = (const char*)g_es + (size_t)(codebase0 + (c) * CHUNK) * 128; \
        uint32_t _dstb = ((c) & 1) ? sb1 : sb0; \
        for (int _i = tid; _i < 1024; _i += 128) { \
            uint32_t _d = _dstb + SW128(_i * 16); \
            asm volatile("cp.async.cg.shared.global [%0], [%1], 16;" \
                :: "r"(_d), "l"(_src + _i * 16) : "memory"); \
        } \
        asm volatile("cp.async.commit_group;" ::: "memory"); \
    } while (0)

    STAGE_CHUNK(0);

    // B ldmatrix.x4 lane addressing. Offset = (nt*8+bcode)*128 + bko, bko<128:
    // bits 7-9 of the offset come ONLY from bcode, so SW128 is nt-invariant.
    // Hoist the swizzle; per-tile address = swbase + nt*1024.
    int bcode = lane & 7;
    int bko = ((lane >> 4) << 5) + (((lane >> 3) & 1) << 4);
    uint32_t bsw0, bsw1;
    {
        uint32_t base0 = (uint32_t)(bcode * 128 + bko);
        uint32_t base1 = (uint32_t)(bcode * 128 + bko + 64);
        bsw0 = SW128(base0);
        bsw1 = SW128(base1);
    }

    for (int c = 0; c < NCHUNKS; c++) {
        if (c + 1 < NCHUNKS) {
            STAGE_CHUNK(c + 1);
            asm volatile("cp.async.wait_group 1;" ::: "memory");
        } else {
            asm volatile("cp.async.wait_group 0;" ::: "memory");
        }
        __syncthreads();

        uint32_t sbB = (c & 1) ? sb1 : sb0;
        int cbase = codebase0 + c * CHUNK;

#pragma unroll 4
        for (int nt = 0; nt < CHUNK / 8; nt++) {
            // B fragments: two x4 loads cover all 4 k-steps
            uint32_t bfr[4][2];
            {
                uint32_t a0 = sbB + bsw0 + nt * 1024;
                asm volatile("ldmatrix.sync.aligned.m8n8.x4.shared.b16 {%0,%1,%2,%3}, [%4];"
                    : "=r"(bfr[0][0]), "=r"(bfr[0][1]), "=r"(bfr[1][0]), "=r"(bfr[1][1]) : "r"(a0));
                uint32_t a1 = sbB + bsw1 + nt * 1024;
                asm volatile("ldmatrix.sync.aligned.m8n8.x4.shared.b16 {%0,%1,%2,%3}, [%4];"
                    : "=r"(bfr[2][0]), "=r"(bfr[2][1]), "=r"(bfr[3][0]), "=r"(bfr[3][1]) : "r"(a1));
            }
            float da[2][4], db[2][4];
#pragma unroll
            for (int mt = 0; mt < 2; mt++) {
#pragma unroll
                for (int i = 0; i < 4; i++) { da[mt][i] = 0.f; db[mt][i] = 0.f; }
                // 4 independent chains: (pass1 even s -> da), (pass1 odd s -> db),
                // (pass2 even -> da), (pass2 odd -> db) interleaved by s parity.
#pragma unroll
                for (int s = 0; s < 4; s++) {
                    float* dd = (s & 1) ? db[mt] : da[mt];
                    asm volatile(
                        "mma.sync.aligned.m16n8k16.row.col.f32.bf16.bf16.f32 "
                        "{%0,%1,%2,%3}, {%4,%5,%6,%7}, {%8,%9}, {%0,%1,%2,%3};"
                        : "+f"(dd[0]), "+f"(dd[1]), "+f"(dd[2]), "+f"(dd[3])
                        : "r"(afr[mt][s][0]), "r"(afr[mt][s][1]), "r"(afr[mt][s][2]), "r"(afr[mt][s][3]),
                          "r"(bfr[s][0]), "r"(bfr[s][1]));
                }
#pragma unroll
                for (int s = 0; s < 4; s++) {
                    int bs = (s + 2) & 3;
                    float* dd = (s & 1) ? db[mt] : da[mt];
                    asm volatile(
                        "mma.sync.aligned.m16n8k16.row.col.f32.bf16.bf16.f32 "
                        "{%0,%1,%2,%3}, {%4,%5,%6,%7}, {%8,%9}, {%0,%1,%2,%3};"
                        : "+f"(dd[0]), "+f"(dd[1]), "+f"(dd[2]), "+f"(dd[3])
                        : "r"(afr[mt][s][0]), "r"(afr[mt][s][1]), "r"(afr[mt][s][2]), "r"(afr[mt][s][3]),
                          "r"(bfr[bs][0]), "r"(bfr[bs][1]));
                }
            }
            // Epilogue: pairwise max over (e0,e1), then lean branchless top-2.
            int nb = cbase + nt * 8 + 2 * (lane & 3);
#pragma unroll
            for (int mt = 0; mt < 2; mt++) {
#pragma unroll
                for (int h = 0; h < 2; h++) {
                    int slot = mt * 2 + h;
                    float v0 = da[mt][h*2+0] + db[mt][h*2+0];
                    float v1 = da[mt][h*2+1] + db[mt][h*2+1];
                    float vm = fmaxf(v0, v1);
                    int im = (v1 > v0) ? nb + 1 : nb;   // tie -> lower index
                    bool p1 = vm > tv1[slot];
                    bool p2 = vm > tv2[slot];
                    ti2[slot] = p1 ? ti1[slot] : (p2 ? im : ti2[slot]);
                    tv2[slot] = fmaxf(tv2[slot], fminf(tv1[slot], vm));
                    ti1[slot] = p1 ? im : ti1[slot];
                    tv1[slot] = fmaxf(tv1[slot], vm);
                }
            }
        }
        __syncthreads();   // all warps done reading buffer before it is restaged
    }

    // ---- merge top-2 across the 4 lanes sharing each row ----
#pragma unroll
    for (int slot = 0; slot < 4; slot++) {
#pragma unroll
        for (int off = 1; off <= 2; off <<= 1) {
            float ov1 = __shfl_xor_sync(0xFFFFFFFFu, tv1[slot], off);
            int   oi1 = __shfl_xor_sync(0xFFFFFFFFu, ti1[slot], off);
            float ov2 = __shfl_xor_sync(0xFFFFFFFFu, tv2[slot], off);
            int   oi2 = __shfl_xor_sync(0xFFFFFFFFu, ti2[slot], off);
            bool o1beats = (ov1 > tv1[slot]) || (ov1 == tv1[slot] && oi1 < ti1[slot]);
            if (o1beats) {
                float nv2; int ni2;
                if (tv1[slot] > ov2 || (tv1[slot] == ov2 && ti1[slot] < oi2)) { nv2 = tv1[slot]; ni2 = ti1[slot]; }
                else { nv2 = ov2; ni2 = oi2; }
                tv1[slot] = ov1; ti1[slot] = oi1;
                tv2[slot] = nv2; ti2[slot] = ni2;
            } else {
                if (ov1 > tv2[slot] || (ov1 == tv2[slot] && oi1 < ti2[slot])) { tv2[slot] = ov1; ti2[slot] = oi1; }
            }
        }
    }
    if ((lane & 3) == 0) {
#pragma unroll
        for (int slot = 0; slot < 4; slot++) {
            int mt = slot >> 1, h = slot & 1;
            int p = pbase + wid * 32 + mt * 16 + h * 8 + (lane >> 2);
            g_cand[p * NCAND + blockIdx.y * 2]     = ti1[slot];
            g_cand[p * NCAND + blockIdx.y * 2 + 1] = ti2[slot];
        }
    }
#undef STAGE_CHUNK
}

// ---------------------------------------------------------------- finalize: exact rescore of NCAND candidates
__global__ void k_finalize() {
    int p = blockIdx.x * blockDim.x + threadIdx.x;
    if (p >= P) return;
    float z[DD];
#pragma unroll
    for (int d = 0; d < DD; d++) z[d] = g_z[p * DD + d];
    float bs = -1e30f;
    int bi = 0x7FFFFFFF;
#pragma unroll 4
    for (int c = 0; c < NCAND; c++) {
        int idx = g_cand[p * NCAND + c];
        const float* e = g_e + idx * DD;
        float s = 0.f;
#pragma unroll
        for (int d = 0; d < DD; d++) s += z[d] * e[d];
        if (s > bs || (s == bs && idx < bi)) { bs = s; bi = idx; }
    }
    g_idx[p] = bi;
    g_s[p] = bs;
    atomicAdd(&g_hist[bi], 1);
}

// ---------------------------------------------------------------- output GEMM (fp32 scalar, f32x2)
__device__ __forceinline__ u64 fma2(u64 a, u64 b, u64 c) {
    u64 d;
    asm("fma.rn.f32x2 %0, %1, %2, %3;" : "=l"(d) : "l"(a), "l"(b), "l"(c));
    return d;
}
__device__ __forceinline__ u64 add2(u64 a, u64 b) {
    u64 d;
    asm("add.rn.f32x2 %0, %1, %2;" : "=l"(d) : "l"(a), "l"(b));
    return d;
}
__device__ __forceinline__ float hsum2(u64 a) {
    unsigned lo, hi;
    asm("mov.b64 {%0, %1}, %2;" : "=r"(lo), "=r"(hi) : "l"(a));
    return __uint_as_float(lo) + __uint_as_float(hi);
}

__global__ void k_output(const float* __restrict__ exp_w,   // [C][D]
                         const float* __restrict__ exp_b,   // [C]
                         float* __restrict__ out) {
    __shared__ float ws[128 * DD];
    __shared__ float wb[128];
    int tid = threadIdx.x;
    int p = blockIdx.x * 128 + tid;
    int b = p >> 10;
    int hw = p & 1023;

    ulonglong2 cz[8];
    {
        int idx = g_idx[p];
        const ulonglong2* cp = (const ulonglong2*)(g_e + idx * DD);
#pragma unroll
        for (int q = 0; q < 8; q++) cz[q] = cp[q];
    }
    float* outp = out + (b * CC) * HW + hw;

    for (int chunk = 0; chunk < 4; chunk++) {
        int c0 = chunk * 128;
        __syncthreads();
        for (int i = tid; i < 128 * DD; i += 128) ws[i] = exp_w[c0 * DD + i];
        wb[tid] = exp_b[c0 + tid];
        __syncthreads();
        for (int ccl = 0; ccl < 128; ccl++) {
            const ulonglong2* wp = (const ulonglong2*)(ws + ccl * DD);
            u64 a0 = 0ull, a1 = 0ull, a2 = 0ull, a3 = 0ull;
#pragma unroll
            for (int q = 0; q < 8; q += 2) {
                ulonglong2 w0 = wp[q];
                ulonglong2 w1 = wp[q + 1];
                a0 = fma2(w0.x, cz[q].x, a0);
                a1 = fma2(w0.y, cz[q].y, a1);
                a2 = fma2(w1.x, cz[q + 1].x, a2);
                a3 = fma2(w1.y, cz[q + 1].y, a3);
            }
            a0 = add2(a0, a1);
            a2 = add2(a2, a3);
            a0 = add2(a0, a2);
            outp[(c0 + ccl) * HW] = hsum2(a0) + wb[ccl];
        }
    }
}

// ---------------------------------------------------------------- scalars
__global__ void k_scalars(float* __restrict__ out) {
    __shared__ float red[256];
    int tid = threadIdx.x;

    float ls = 0.f;
    for (int i = tid; i < P; i += 256) ls += g_s[i];
    red[tid] = ls;
    __syncthreads();
    for (int off = 128; off > 0; off >>= 1) {
        if (tid < off) red[tid] += red[tid + off];
        __syncthreads();
    }
    float sum_s = red[0];
    __syncthreads();

    float hs = 0.f;
    const float invP = 1.0f / (float)P;
    for (int i = tid; i < NN; i += 256) {
        float u = (float)g_hist[i] * invP;
        hs += -u * logf(u + 1e-6f);
    }
    red[tid] = hs;
    __syncthreads();
    for (int off = 128; off > 0; off >>= 1) {
        if (tid < off) red[tid] += red[tid + off];
        __syncthreads();
    }
    if (tid == 0) {
        out[OUT_ELEMS]     = (2.f * (float)P - 2.f * sum_s) / ((float)P * (float)DD);
        out[OUT_ELEMS + 1] = expf(red[0]);
    }
}

// ---------------------------------------------------------------- launch
extern "C" void kernel_launch(void* const* d_in, const int* in_sizes, int n_in,
                              void* d_out, int out_size) {
    const float* encodings = (const float*)d_in[0];
    const float* emb_weight = (const float*)d_in[1];
    const float* proj_w = (const float*)d_in[2];
    const float* proj_b = (const float*)d_in[3];
    const float* exp_w = (const float*)d_in[4];
    const float* exp_b = (const float*)d_in[5];
    float* out = (float*)d_out;

    k_init<<<NN / 256, 256>>>();
    k_norm_emb<<<NN / 128, 128>>>(emb_weight);
    k_project<<<P / 128, 128>>>(encodings, proj_w, proj_b);
    k_search_mma<<<dim3(P / MTILE, NSPLITY), 128>>>();
    k_finalize<<<P / 256, 256>>>();
    k_output<<<P / 128, 128>>>(exp_w, exp_b, out);
    k_scalars<<<1, 256>>>(out);
}